// round 2
// baseline (speedup 1.0000x reference)
#include <cuda_runtime.h>

#define NB  4
#define NSQ 512
#define NSK 512
#define ND  512
#define NS  128

typedef unsigned long long ull;

// ---- packed f32x2 helpers (Blackwell FFMA2 path) ----
__device__ __forceinline__ void fma2(ull& d, ull a, ull b) {
    asm("fma.rn.f32x2 %0, %1, %2, %0;" : "+l"(d) : "l"(a), "l"(b));
}
__device__ __forceinline__ ull pack2(float x, float y) {
    ull r; asm("mov.b64 %0, {%1, %2};" : "=l"(r) : "f"(x), "f"(y)); return r;
}
__device__ __forceinline__ float2 unpack2(ull v) {
    float2 r; asm("mov.b64 {%0, %1}, %2;" : "=f"(r.x), "=f"(r.y) : "l"(v)); return r;
}

// ---- scratch (allocation-free) ----
__device__ __align__(16) float g_Wqh[ND * NS];
__device__ __align__(16) float g_Wkh[ND * NS];
__device__ __align__(16) float g_cA[NS];
__device__ __align__(16) float g_cK[NS];
__device__ __align__(16) float g_sg[NS];           // +-0.5 by sign of w2
__device__ __align__(16) float g_A2[NB * NSQ * NS]; // (q@Wqh + cA) * w2
__device__ __align__(16) float g_K2[NB * NSK * NS]; // (k@Wkh + cK) * w2
__device__ __align__(16) float g_CA[NB * NSQ];      // 0.5 * rowsum(A2)
__device__ __align__(16) float g_CK[NB * NSK];      // 0.5 * rowsum(K2)

// ---------------------------------------------------------------------------
// fold weights: Wqh = Wq @ W1[:S], Wkh = Wk @ W1[S:]
// grid (64, 2), 128 threads; block computes 8 d-rows, reads W1 once per block
// ---------------------------------------------------------------------------
__global__ void fold_weights_kernel(const float* __restrict__ Wq,
                                    const float* __restrict__ Wk,
                                    const float* __restrict__ W1) {
    int v = blockIdx.y, d0 = blockIdx.x * 8, s = threadIdx.x;
    __shared__ float wr[8][NS];
    const float* Wsrc = v ? Wk : Wq;
#pragma unroll
    for (int j = 0; j < 8; j++) wr[j][s] = Wsrc[(d0 + j) * NS + s];
    __syncthreads();
    const float* W1p = W1 + (v ? NS * NS : 0);
    float acc[8] = {};
#pragma unroll 4
    for (int t = 0; t < NS; t++) {
        float w = W1p[t * NS + s];
#pragma unroll
        for (int j = 0; j < 8; j++) acc[j] = fmaf(wr[j][t], w, acc[j]);
    }
    float* O = v ? g_Wkh : g_Wqh;
#pragma unroll
    for (int j = 0; j < 8; j++) O[(d0 + j) * NS + s] = acc[j];
}

// cA = b1 + bq@W1[:S]; cK = bk@W1[S:]; sg = sign(w2)*0.5
__global__ void fold_bias_kernel(const float* __restrict__ bq,
                                 const float* __restrict__ bk,
                                 const float* __restrict__ W1,
                                 const float* __restrict__ b1,
                                 const float* __restrict__ W2) {
    int s = threadIdx.x;
    float a = b1[s], c = 0.f;
    for (int t = 0; t < NS; t++) {
        a = fmaf(bq[t], W1[t * NS + s], a);
        c = fmaf(bk[t], W1[(NS + t) * NS + s], c);
    }
    g_cA[s] = a;
    g_cK[s] = c;
    g_sg[s] = (W2[s] >= 0.f) ? 0.5f : -0.5f;
}

// ---------------------------------------------------------------------------
// proj: A2 = (X @ Wfold + cb) * w2, plus row sums CA = 0.5*rowsum(A2)
// M=2048, K=512, N=128. BM=32, BN=128 (full S), BK=16, 256 thr, 2q x 8d packed
// grid (64, 2)
// ---------------------------------------------------------------------------
__global__ __launch_bounds__(256) void proj_kernel(const float* __restrict__ Xq,
                                                   const float* __restrict__ Xk,
                                                   const float* __restrict__ W2) {
    int v = blockIdx.y;
    const float* X  = v ? Xk : Xq;
    const float* Wf = v ? g_Wkh : g_Wqh;
    const float* cb = v ? g_cK : g_cA;
    float* O        = v ? g_K2 : g_A2;
    float* CS       = v ? g_CK : g_CA;

    int m0 = blockIdx.x * 32;
    int tid = threadIdx.x, tx = tid & 15, ty = tid >> 4;

    __shared__ float As[16][33];
    __shared__ float Bs[16][132];

    ull acc[2][4] = {};

    int r  = tid >> 3, c2 = (tid & 7) * 2;     // X loader coords
    int rw = tid >> 4, cw = (tid & 15) * 8;    // W loader coords

    for (int k0 = 0; k0 < ND; k0 += 16) {
        __syncthreads();
        float2 xv = *(const float2*)&X[(m0 + r) * ND + k0 + c2];
        As[c2][r] = xv.x; As[c2 + 1][r] = xv.y;
        float4 w0 = *(const float4*)&Wf[(k0 + rw) * NS + cw];
        float4 w1 = *(const float4*)&Wf[(k0 + rw) * NS + cw + 4];
        *(float4*)&Bs[rw][cw] = w0;
        *(float4*)&Bs[rw][cw + 4] = w1;
        __syncthreads();
#pragma unroll
        for (int kk = 0; kk < 16; kk++) {
            float a0 = As[kk][ty * 2], a1 = As[kk][ty * 2 + 1];
            ull ap0 = pack2(a0, a0), ap1 = pack2(a1, a1);
            ulonglong2 b0 = *(ulonglong2*)&Bs[kk][tx * 8];
            ulonglong2 b1 = *(ulonglong2*)&Bs[kk][tx * 8 + 4];
            fma2(acc[0][0], ap0, b0.x); fma2(acc[0][1], ap0, b0.y);
            fma2(acc[0][2], ap0, b1.x); fma2(acc[0][3], ap0, b1.y);
            fma2(acc[1][0], ap1, b0.x); fma2(acc[1][1], ap1, b0.y);
            fma2(acc[1][2], ap1, b1.x); fma2(acc[1][3], ap1, b1.y);
        }
    }

    int d0 = tx * 8;
    float4 cb0 = *(const float4*)&cb[d0];
    float4 cb1 = *(const float4*)&cb[d0 + 4];
    float4 w20 = *(const float4*)&W2[d0];
    float4 w21 = *(const float4*)&W2[d0 + 4];

#pragma unroll
    for (int j = 0; j < 2; j++) {
        int row = m0 + ty * 2 + j;
        float2 p0 = unpack2(acc[j][0]), p1 = unpack2(acc[j][1]);
        float2 p2 = unpack2(acc[j][2]), p3 = unpack2(acc[j][3]);
        float4 o0, o1;
        o0.x = (p0.x + cb0.x) * w20.x; o0.y = (p0.y + cb0.y) * w20.y;
        o0.z = (p1.x + cb0.z) * w20.z; o0.w = (p1.y + cb0.w) * w20.w;
        o1.x = (p2.x + cb1.x) * w21.x; o1.y = (p2.y + cb1.y) * w21.y;
        o1.z = (p3.x + cb1.z) * w21.z; o1.w = (p3.y + cb1.w) * w21.w;
        *(float4*)&O[row * NS + d0] = o0;
        *(float4*)&O[row * NS + d0 + 4] = o1;
        float rs = o0.x + o0.y + o0.z + o0.w + o1.x + o1.y + o1.z + o1.w;
#pragma unroll
        for (int o = 8; o; o >>= 1) rs += __shfl_xor_sync(0xffffffffu, rs, o);
        if (tx == 0) CS[row] = 0.5f * rs;
    }
}

// ---------------------------------------------------------------------------
// scores + softmax + attn write.
// scores[q,k] = CA[q]+CK[k]+b2 + sum_s sg[s]*|A2[q,s]+K2[k,s]|
// grid NB*NSQ/8 = 256 blocks, 256 threads, ~91KB smem -> 2 CTAs/SM
// ---------------------------------------------------------------------------
#define TQ  8
#define KMP 132
#define SCP 516

__global__ __launch_bounds__(256) void score_kernel(const int* __restrict__ mask,
                                                    const float* __restrict__ b2,
                                                    float* __restrict__ attn_out) {
    extern __shared__ float sm[];
    float* qcs = sm;                    // TQ*NS   = 1024 f
    float* sgs = qcs + TQ * NS;         // 128 f
    float* cks = sgs + NS;              // 512 f
    float* cas = cks + NSK;             // 16 f (8 used)
    float* kms = cas + 16;              // 128*132 = 16896 f
    float* scT = kms + 128 * KMP;       // TQ*516  = 4128 f

    int bx = blockIdx.x;
    int b  = bx >> 6;
    int q0 = (bx & 63) * TQ;
    int tid = threadIdx.x;

    // stage
    {
        const float4* A4 = (const float4*)&g_A2[(b * NSQ + q0) * NS];
        ((float4*)qcs)[tid] = A4[tid];                          // 256 float4
        if (tid < 32)  ((float4*)sgs)[tid] = ((const float4*)g_sg)[tid];
        if (tid < 128) ((float4*)cks)[tid] = ((const float4*)(g_CK + b * NSK))[tid];
        if (tid < TQ)  cas[tid] = g_CA[b * NSQ + q0 + tid] + b2[0];
    }

    int kk = tid & 127;
    int qh = (tid >> 7) * 4;
    const float* qp = qcs + qh * NS;

    for (int k0 = 0; k0 < NSK; k0 += 128) {
        __syncthreads();
        const float4* K4 = (const float4*)&g_K2[(b * NSK + k0) * NS];
        for (int i = tid; i < 128 * 32; i += 256) {
            int kr = i >> 5, s4 = i & 31;
            *(float4*)&kms[kr * KMP + s4 * 4] = K4[i];
        }
        __syncthreads();

        float acc0 = 0.f, acc1 = 0.f, acc2 = 0.f, acc3 = 0.f;
#pragma unroll 8
        for (int s = 0; s < NS; s += 4) {
            float4 kv = *(float4*)&kms[kk * KMP + s];
            float4 sg = *(float4*)&sgs[s];
            float4 v0 = *(float4*)&qp[s];
            float4 v1 = *(float4*)&qp[NS + s];
            float4 v2 = *(float4*)&qp[2 * NS + s];
            float4 v3 = *(float4*)&qp[3 * NS + s];
            acc0 = fmaf(sg.x, fabsf(v0.x + kv.x), acc0);
            acc0 = fmaf(sg.y, fabsf(v0.y + kv.y), acc0);
            acc0 = fmaf(sg.z, fabsf(v0.z + kv.z), acc0);
            acc0 = fmaf(sg.w, fabsf(v0.w + kv.w), acc0);
            acc1 = fmaf(sg.x, fabsf(v1.x + kv.x), acc1);
            acc1 = fmaf(sg.y, fabsf(v1.y + kv.y), acc1);
            acc1 = fmaf(sg.z, fabsf(v1.z + kv.z), acc1);
            acc1 = fmaf(sg.w, fabsf(v1.w + kv.w), acc1);
            acc2 = fmaf(sg.x, fabsf(v2.x + kv.x), acc2);
            acc2 = fmaf(sg.y, fabsf(v2.y + kv.y), acc2);
            acc2 = fmaf(sg.z, fabsf(v2.z + kv.z), acc2);
            acc2 = fmaf(sg.w, fabsf(v2.w + kv.w), acc2);
            acc3 = fmaf(sg.x, fabsf(v3.x + kv.x), acc3);
            acc3 = fmaf(sg.y, fabsf(v3.y + kv.y), acc3);
            acc3 = fmaf(sg.z, fabsf(v3.z + kv.z), acc3);
            acc3 = fmaf(sg.w, fabsf(v3.w + kv.w), acc3);
        }

        int kg = k0 + kk;
        float ckv = cks[kg];
        const int* mrow = mask + (b * NSQ + q0 + qh) * NSK + kg;
        float sc[4] = {acc0, acc1, acc2, acc3};
#pragma unroll
        for (int j = 0; j < 4; j++) {
            float s = sc[j] + cas[qh + j] + ckv;
            if (mrow[j * NSK] == 0) s = -1e9f;
            scT[(qh + j) * SCP + kg] = s;
        }
    }
    __syncthreads();

    // softmax: warp w handles q=w; write normalized attn to gmem
    {
        int q = tid >> 5, lane = tid & 31;
        float4 v[4];
        float mx = -3.0e38f;
#pragma unroll
        for (int j = 0; j < 4; j++) {
            v[j] = *(float4*)&scT[q * SCP + j * 128 + lane * 4];
            mx = fmaxf(mx, fmaxf(fmaxf(v[j].x, v[j].y), fmaxf(v[j].z, v[j].w)));
        }
#pragma unroll
        for (int o = 16; o; o >>= 1) mx = fmaxf(mx, __shfl_xor_sync(0xffffffffu, mx, o));
        float sum = 0.f;
#pragma unroll
        for (int j = 0; j < 4; j++) {
            v[j].x = __expf(v[j].x - mx); v[j].y = __expf(v[j].y - mx);
            v[j].z = __expf(v[j].z - mx); v[j].w = __expf(v[j].w - mx);
            sum += v[j].x + v[j].y + v[j].z + v[j].w;
        }
#pragma unroll
        for (int o = 16; o; o >>= 1) sum += __shfl_xor_sync(0xffffffffu, sum, o);
        float inv = 1.0f / sum;
        float* arow = attn_out + (b * NSQ + q0 + q) * NSK;
#pragma unroll
        for (int j = 0; j < 4; j++) {
            float4 w;
            w.x = v[j].x * inv; w.y = v[j].y * inv;
            w.z = v[j].z * inv; w.w = v[j].w * inv;
            *(float4*)&arow[j * 128 + lane * 4] = w;
        }
    }
}

// ---------------------------------------------------------------------------
// AV GEMM: out[b,q,d] = sum_k attn[b,q,k] * V[b,k,d]
// BM=64(q) x BN=64(d) x BK=16, 256 thr, per-thread 4q x 4d via f32x2 q-pairs
// grid (8, 8, 4)
// ---------------------------------------------------------------------------
__global__ __launch_bounds__(256) void av_kernel(const float* __restrict__ attn,
                                                 const float* __restrict__ V,
                                                 float* __restrict__ out) {
    int b = blockIdx.z;
    int q0 = blockIdx.x * 64, d0 = blockIdx.y * 64;
    int tid = threadIdx.x, tx = tid & 15, ty = tid >> 4;

    __shared__ float As[16][68];   // transposed attn tile [k][q], 16B-aligned rows
    __shared__ float Bs[16][64];

    ull acc[2][4] = {};

    const float* Ab = attn + (b * NSQ + q0) * NSK;
    const float* Vb = V + b * NSK * ND + d0;

    int ra = tid >> 2, ca = (tid & 3) * 4;   // attn loader
    int rb = tid >> 4, cb = (tid & 15) * 4;  // V loader

    for (int k0 = 0; k0 < NSK; k0 += 16) {
        __syncthreads();
        float4 a = *(const float4*)&Ab[ra * NSK + k0 + ca];
        As[ca][ra] = a.x; As[ca + 1][ra] = a.y;
        As[ca + 2][ra] = a.z; As[ca + 3][ra] = a.w;
        *(float4*)&Bs[rb][cb] = *(const float4*)&Vb[(k0 + rb) * ND + cb];
        __syncthreads();
#pragma unroll
        for (int kk = 0; kk < 16; kk++) {
            ulonglong2 a2 = *(ulonglong2*)&As[kk][ty * 4];
            float4 bv = *(float4*)&Bs[kk][tx * 4];
            ull b0 = pack2(bv.x, bv.x), b1 = pack2(bv.y, bv.y);
            ull b2p = pack2(bv.z, bv.z), b3 = pack2(bv.w, bv.w);
            fma2(acc[0][0], a2.x, b0); fma2(acc[0][1], a2.x, b1);
            fma2(acc[0][2], a2.x, b2p); fma2(acc[0][3], a2.x, b3);
            fma2(acc[1][0], a2.y, b0); fma2(acc[1][1], a2.y, b1);
            fma2(acc[1][2], a2.y, b2p); fma2(acc[1][3], a2.y, b3);
        }
    }

    float* Ob = out + (b * NSQ + q0) * ND + d0;
#pragma unroll
    for (int qp = 0; qp < 2; qp++) {
        int q = ty * 4 + qp * 2;
#pragma unroll
        for (int j = 0; j < 4; j++) {
            float2 p = unpack2(acc[qp][j]);
            Ob[q * ND + tx * 4 + j] = p.x;
            Ob[(q + 1) * ND + tx * 4 + j] = p.y;
        }
    }
}

// ---------------------------------------------------------------------------
#define SMEM_SC ((TQ * NS + NS + NSK + 16 + 128 * KMP + TQ * SCP) * 4)

extern "C" void kernel_launch(void* const* d_in, const int* in_sizes, int n_in,
                              void* d_out, int out_size) {
    const float* query = (const float*)d_in[0];
    const float* key   = (const float*)d_in[1];
    const float* value = (const float*)d_in[2];
    const int*   mask  = (const int*)d_in[3];
    const float* Wq = (const float*)d_in[4];
    const float* bq = (const float*)d_in[5];
    const float* Wk = (const float*)d_in[6];
    const float* bk = (const float*)d_in[7];
    const float* W1 = (const float*)d_in[8];
    const float* b1 = (const float*)d_in[9];
    const float* W2 = (const float*)d_in[10];
    const float* b2 = (const float*)d_in[11];

    float* out  = (float*)d_out;
    float* attn = out + NB * NSQ * ND;

    cudaFuncSetAttribute(score_kernel,
                         cudaFuncAttributeMaxDynamicSharedMemorySize, SMEM_SC);

    fold_weights_kernel<<<dim3(64, 2), 128>>>(Wq, Wk, W1);
    fold_bias_kernel<<<1, NS>>>(bq, bk, W1, b1, W2);
    proj_kernel<<<dim3(64, 2), 256>>>(query, key, W2);
    score_kernel<<<NB * NSQ / TQ, 256, SMEM_SC>>>(mask, b2, attn);
    av_kernel<<<dim3(8, 8, 4), 256>>>(attn, value, out);
}